// round 14
// baseline (speedup 1.0000x reference)
#include <cuda_runtime.h>
#include <cuda_bf16.h>
#include <math.h>
#include <stdint.h>

#define BB     32
#define LL     512
#define DDIM   192
#define HH     6
#define NDEPTH 12
#define NROWS  (BB * LL)          // 16384

// ---------------- scratch (device globals) ----------------------------------
__device__ __align__(16) float g_x[NROWS * DDIM];
// activation bf16 hi/lo planes
__device__ __align__(16) __nv_bfloat16 g_hh[NROWS * DDIM];
__device__ __align__(16) __nv_bfloat16 g_hl[NROWS * DDIM];
__device__ __align__(16) __nv_bfloat16 g_qh[NROWS * 576];
__device__ __align__(16) __nv_bfloat16 g_ql[NROWS * 576];
__device__ __align__(16) __nv_bfloat16 g_oh[NROWS * DDIM];
__device__ __align__(16) __nv_bfloat16 g_ol[NROWS * DDIM];
__device__ __align__(16) __nv_bfloat16 g_fh[NROWS * 768];
__device__ __align__(16) __nv_bfloat16 g_fl[NROWS * 768];
// weight bf16 hi/lo planes
__device__ __align__(16) __nv_bfloat16 g_wqh[NDEPTH * 576 * 192];
__device__ __align__(16) __nv_bfloat16 g_wql[NDEPTH * 576 * 192];
__device__ __align__(16) __nv_bfloat16 g_woh[NDEPTH * 192 * 192];
__device__ __align__(16) __nv_bfloat16 g_wol[NDEPTH * 192 * 192];
__device__ __align__(16) __nv_bfloat16 g_w1h[NDEPTH * 768 * 192];
__device__ __align__(16) __nv_bfloat16 g_w1l[NDEPTH * 768 * 192];
__device__ __align__(16) __nv_bfloat16 g_w2h[NDEPTH * 192 * 768];
__device__ __align__(16) __nv_bfloat16 g_w2l[NDEPTH * 192 * 768];

// ---------------- helpers ----------------------------------------------------
__device__ __forceinline__ uint32_t smem_u32(const void* p) {
    uint32_t a;
    asm("{ .reg .u64 t; cvta.to.shared.u64 t, %1; cvt.u32.u64 %0, t; }"
        : "=r"(a) : "l"(p));
    return a;
}

// fp32x8 -> bf16 hi plane + lo plane (16B each)
__device__ __forceinline__ void cvt8(__nv_bfloat16* ph, __nv_bfloat16* pl,
                                     float4 a, float4 b) {
    __nv_bfloat162 h0 = __floats2bfloat162_rn(a.x, a.y);
    __nv_bfloat162 h1 = __floats2bfloat162_rn(a.z, a.w);
    __nv_bfloat162 h2 = __floats2bfloat162_rn(b.x, b.y);
    __nv_bfloat162 h3 = __floats2bfloat162_rn(b.z, b.w);
    float2 f0 = __bfloat1622float2(h0), f1 = __bfloat1622float2(h1);
    float2 f2 = __bfloat1622float2(h2), f3 = __bfloat1622float2(h3);
    __nv_bfloat162 l0 = __floats2bfloat162_rn(a.x - f0.x, a.y - f0.y);
    __nv_bfloat162 l1 = __floats2bfloat162_rn(a.z - f1.x, a.w - f1.y);
    __nv_bfloat162 l2 = __floats2bfloat162_rn(b.x - f2.x, b.y - f2.y);
    __nv_bfloat162 l3 = __floats2bfloat162_rn(b.z - f3.x, b.w - f3.y);
    uint4 hv, lv;
    hv.x = *(uint32_t*)&h0; hv.y = *(uint32_t*)&h1;
    hv.z = *(uint32_t*)&h2; hv.w = *(uint32_t*)&h3;
    lv.x = *(uint32_t*)&l0; lv.y = *(uint32_t*)&l1;
    lv.z = *(uint32_t*)&l2; lv.w = *(uint32_t*)&l3;
    *reinterpret_cast<uint4*>(ph) = hv;
    *reinterpret_cast<uint4*>(pl) = lv;
}

#define LDSM4(r, addr) \
    asm volatile("ldmatrix.sync.aligned.m8n8.x4.shared.b16 {%0,%1,%2,%3}, [%4];" \
        : "=r"((r)[0]), "=r"((r)[1]), "=r"((r)[2]), "=r"((r)[3]) : "r"(addr))
#define LDSM2(r, addr) \
    asm volatile("ldmatrix.sync.aligned.m8n8.x2.shared.b16 {%0,%1}, [%2];" \
        : "=r"((r)[0]), "=r"((r)[1]) : "r"(addr))
#define LDSM2T(r, addr) \
    asm volatile("ldmatrix.sync.aligned.m8n8.x2.trans.shared.b16 {%0,%1}, [%2];" \
        : "=r"((r)[0]), "=r"((r)[1]) : "r"(addr))
#define MMA16816(c, a, b) \
    asm volatile("mma.sync.aligned.m16n8k16.row.col.f32.bf16.bf16.f32 " \
        "{%0,%1,%2,%3}, {%4,%5,%6,%7}, {%8,%9}, {%0,%1,%2,%3};" \
        : "+f"((c)[0]), "+f"((c)[1]), "+f"((c)[2]), "+f"((c)[3]) \
        : "r"((a)[0]), "r"((a)[1]), "r"((a)[2]), "r"((a)[3]), \
          "r"((b)[0]), "r"((b)[1]))

// ---------------- weight fp32 -> hi/lo plane convert --------------------------
__global__ __launch_bounds__(256) void convw_kernel(
    const float* __restrict__ w, __nv_bfloat16* __restrict__ hi,
    __nv_bfloat16* __restrict__ lo, int n8)
{
    int i = blockIdx.x * 256 + threadIdx.x;
    if (i >= n8) return;
    const float* p = w + (size_t)i * 8;
    cvt8(hi + (size_t)i * 8, lo + (size_t)i * 8,
         *reinterpret_cast<const float4*>(p),
         *reinterpret_cast<const float4*>(p + 4));
}

// ---------------- embedding --------------------------------------------------
__global__ __launch_bounds__(256) void embed_kernel(
    const int* __restrict__ seq, const float* __restrict__ emb,
    float* __restrict__ x)
{
    int idx = blockIdx.x * 256 + threadIdx.x;
    int r = idx / DDIM;
    int c = idx - r * DDIM;
    x[idx] = emb[seq[r] * DDIM + c];
}

// ---------------- layernorm -> bf16 hi/lo planes ------------------------------
__global__ __launch_bounds__(256) void ln_kernel(
    const float* __restrict__ x, const float* __restrict__ gam,
    const float* __restrict__ bet,
    __nv_bfloat16* __restrict__ oh, __nv_bfloat16* __restrict__ ol)
{
    int gtid = blockIdx.x * 256 + threadIdx.x;
    int row  = gtid >> 5;
    int lane = threadIdx.x & 31;
    const float* xr = x + (size_t)row * DDIM;
    float v[6];
    float s = 0.f;
#pragma unroll
    for (int j = 0; j < 6; j++) { v[j] = xr[lane + 32 * j]; s += v[j]; }
#pragma unroll
    for (int o = 16; o; o >>= 1) s += __shfl_xor_sync(0xffffffffu, s, o);
    float mu = s * (1.0f / DDIM);
    float sq = 0.f;
#pragma unroll
    for (int j = 0; j < 6; j++) { float d = v[j] - mu; sq += d * d; }
#pragma unroll
    for (int o = 16; o; o >>= 1) sq += __shfl_xor_sync(0xffffffffu, sq, o);
    float rstd = rsqrtf(sq * (1.0f / DDIM) + 1e-5f);
#pragma unroll
    for (int j = 0; j < 6; j++) {
        int c = lane + 32 * j;
        float y = (v[j] - mu) * rstd * gam[c] + bet[c];
        __nv_bfloat16 hp = __float2bfloat16(y);
        oh[(size_t)row * DDIM + c] = hp;
        ol[(size_t)row * DDIM + c] = __float2bfloat16(y - __bfloat162float(hp));
    }
}

// ---------------- mma.sync bf16-split GEMM (plane inputs) ---------------------
// EPI: 0 = +bias -> fp32 C ; 1 = +bias,gelu -> planes ; 2 = +bias,+resid -> fp32 C ;
//      3 = +bias -> planes
#define GMS 40

template<int EPI>
__global__ __launch_bounds__(256, 2) void gemm_mma(
    const __nv_bfloat16* __restrict__ Ah, const __nv_bfloat16* __restrict__ Al,
    const __nv_bfloat16* __restrict__ Wh, const __nv_bfloat16* __restrict__ Wl,
    const float* __restrict__ bias, const float* __restrict__ resid,
    float* __restrict__ C, __nv_bfloat16* __restrict__ Ch,
    __nv_bfloat16* __restrict__ Cl, int N, int K)
{
    __shared__ __nv_bfloat16 sAh[128 * GMS];
    __shared__ __nv_bfloat16 sAl[128 * GMS];
    __shared__ __nv_bfloat16 sWh[64 * GMS];
    __shared__ __nv_bfloat16 sWl[64 * GMS];

    const int tid  = threadIdx.x;
    const int wid  = tid >> 5;
    const int lane = tid & 31;
    const int m0 = blockIdx.y * 128;
    const int n0 = blockIdx.x * 64;
    const int wm = wid & 3;
    const int wn = wid >> 2;

    float acc[2][4][4];
#pragma unroll
    for (int i = 0; i < 2; i++)
#pragma unroll
        for (int j = 0; j < 4; j++)
#pragma unroll
            for (int k = 0; k < 4; k++) acc[i][j][k] = 0.f;

    uint32_t adrA[2], adrAl[2];
#pragma unroll
    for (int mf = 0; mf < 2; mf++) {
        int r  = wm * 32 + mf * 16 + ((lane >> 3) & 1) * 8 + (lane & 7);
        int kc = (lane >> 4) * 8;
        adrA[mf]  = smem_u32(&sAh[r * GMS + kc]);
        adrAl[mf] = smem_u32(&sAl[r * GMS + kc]);
    }
    uint32_t adrB[4], adrBl[4];
#pragma unroll
    for (int nf = 0; nf < 4; nf++) {
        int r  = wn * 32 + nf * 8 + (lane & 7);
        int kc = ((lane >> 3) & 1) * 8;
        adrB[nf]  = smem_u32(&sWh[r * GMS + kc]);
        adrBl[nf] = smem_u32(&sWl[r * GMS + kc]);
    }

    const int frow = tid >> 1;      // 0..127
    const int fh   = (tid & 1) * 16;

    for (int k0 = 0; k0 < K; k0 += 32) {
        {   // A planes: 128 rows x 32 bf16
            const __nv_bfloat16* ap = Ah + (size_t)(m0 + frow) * K + k0 + fh;
            const __nv_bfloat16* lp = Al + (size_t)(m0 + frow) * K + k0 + fh;
            *reinterpret_cast<uint4*>(&sAh[frow * GMS + fh]) =
                *reinterpret_cast<const uint4*>(ap);
            *reinterpret_cast<uint4*>(&sAh[frow * GMS + fh + 8]) =
                *reinterpret_cast<const uint4*>(ap + 8);
            *reinterpret_cast<uint4*>(&sAl[frow * GMS + fh]) =
                *reinterpret_cast<const uint4*>(lp);
            *reinterpret_cast<uint4*>(&sAl[frow * GMS + fh + 8]) =
                *reinterpret_cast<const uint4*>(lp + 8);
            if (tid < 128) {   // W planes: 64 rows
                int wrow = tid >> 1;
                int wh2  = (tid & 1) * 16;
                const __nv_bfloat16* wp = Wh + (size_t)(n0 + wrow) * K + k0 + wh2;
                const __nv_bfloat16* wl = Wl + (size_t)(n0 + wrow) * K + k0 + wh2;
                *reinterpret_cast<uint4*>(&sWh[wrow * GMS + wh2]) =
                    *reinterpret_cast<const uint4*>(wp);
                *reinterpret_cast<uint4*>(&sWh[wrow * GMS + wh2 + 8]) =
                    *reinterpret_cast<const uint4*>(wp + 8);
                *reinterpret_cast<uint4*>(&sWl[wrow * GMS + wh2]) =
                    *reinterpret_cast<const uint4*>(wl);
                *reinterpret_cast<uint4*>(&sWl[wrow * GMS + wh2 + 8]) =
                    *reinterpret_cast<const uint4*>(wl + 8);
            }
        }
        __syncthreads();

#pragma unroll
        for (int kk = 0; kk < 2; kk++) {
            uint32_t ah[2][4], al[2][4], bh[4][2], bl[4][2];
            const uint32_t ko = kk * 32;
#pragma unroll
            for (int mf = 0; mf < 2; mf++) {
                LDSM4(ah[mf], adrA[mf] + ko);
                LDSM4(al[mf], adrAl[mf] + ko);
            }
#pragma unroll
            for (int nf = 0; nf < 4; nf++) {
                LDSM2(bh[nf], adrB[nf] + ko);
                LDSM2(bl[nf], adrBl[nf] + ko);
            }
#pragma unroll
            for (int mf = 0; mf < 2; mf++)
#pragma unroll
                for (int nf = 0; nf < 4; nf++) {
                    MMA16816(acc[mf][nf], ah[mf], bh[nf]);
                    MMA16816(acc[mf][nf], ah[mf], bl[nf]);
                    MMA16816(acc[mf][nf], al[mf], bh[nf]);
                }
        }
        __syncthreads();
    }

    const int g   = lane >> 2;
    const int tig = lane & 3;
#pragma unroll
    for (int mf = 0; mf < 2; mf++) {
#pragma unroll
        for (int nf = 0; nf < 4; nf++) {
            int m = m0 + wm * 32 + mf * 16 + g;
            int n = n0 + wn * 32 + nf * 8 + 2 * tig;
            float b0 = bias[n], b1 = bias[n + 1];
#pragma unroll
            for (int half = 0; half < 2; half++) {
                int mm = m + half * 8;
                float rx = acc[mf][nf][half * 2 + 0] + b0;
                float ry = acc[mf][nf][half * 2 + 1] + b1;
                if (EPI == 1) {
                    rx = 0.5f * rx * (1.0f + erff(rx * 0.70710678118654752f));
                    ry = 0.5f * ry * (1.0f + erff(ry * 0.70710678118654752f));
                }
                if (EPI == 2) {
                    float2 rv = *reinterpret_cast<const float2*>(
                        &resid[(size_t)mm * N + n]);
                    rx += rv.x; ry += rv.y;
                }
                if (EPI == 0 || EPI == 2) {
                    *reinterpret_cast<float2*>(&C[(size_t)mm * N + n]) =
                        make_float2(rx, ry);
                } else {
                    __nv_bfloat162 hb = __floats2bfloat162_rn(rx, ry);
                    float2 hf = __bfloat1622float2(hb);
                    __nv_bfloat162 lb =
                        __floats2bfloat162_rn(rx - hf.x, ry - hf.y);
                    *reinterpret_cast<uint32_t*>(&Ch[(size_t)mm * N + n]) =
                        *(uint32_t*)&hb;
                    *reinterpret_cast<uint32_t*>(&Cl[(size_t)mm * N + n]) =
                        *(uint32_t*)&lb;
                }
            }
        }
    }
}

// ---------------- fused tensor-core attention (plane inputs/outputs) ----------
// Block = (32-q tile, head, batch), 8 warps. QKV already split into bf16 hi/lo
// planes by the QKV GEMM -> all SMEM fills are plain copies. V stored [k][d]
// like K and fed to MMA via ldmatrix.trans (no transpose pass). V planes alias
// the dead K region. P hi/lo written in-place over dead fp32 score rows.
#define SP    516      // sS stride (fp32)
#define SROWB 2064     // P row bytes: 1024B hi + lo @ +1040
#define QS    40
#define KS    40
// float-unit offsets
#define OFF_QH  16512
#define OFF_QL  17152
#define OFF_KH  17792
#define OFF_KL  20352
#define OFF_REL 22912
#define ATTN_SMEM_BYTES ((OFF_REL + 68) * 4)

__global__ __launch_bounds__(256) void attn_kernel(
    const __nv_bfloat16* __restrict__ qh, const __nv_bfloat16* __restrict__ ql,
    const float* __restrict__ bppm,
    const float* __restrict__ pair_w, const float* __restrict__ pair_b,
    const float* __restrict__ relpos_w, const float* __restrict__ relpos_b,
    __nv_bfloat16* __restrict__ oh, __nv_bfloat16* __restrict__ ol)
{
    extern __shared__ float smf[];
    float* sS = smf;
    uint8_t* uP = (uint8_t*)smf;
    __nv_bfloat16* sQh = (__nv_bfloat16*)(smf + OFF_QH);
    __nv_bfloat16* sQl = (__nv_bfloat16*)(smf + OFF_QL);
    __nv_bfloat16* sKh = (__nv_bfloat16*)(smf + OFF_KH);   // aliased by V later
    __nv_bfloat16* sKl = (__nv_bfloat16*)(smf + OFF_KL);
    float* srel = smf + OFF_REL;

    const int tid  = threadIdx.x;
    const int wid  = tid >> 5;
    const int lane = tid & 31;
    const int q0 = blockIdx.x * 32;
    const int h  = blockIdx.y;
    const int b  = blockIdx.z;

    if (tid < 65) srel[tid] = relpos_w[h * 65 + tid];
    const float pw = pair_w[h];
    const float cb = pair_b[h] + relpos_b[h];
    const float scale = 0.17677669529663687f;   // 1/sqrt(32)

    // ---- Q planes -> sQh/sQl (copies) ----
    if (tid < 128) {
        int qq = tid >> 2, d0 = (tid & 3) * 8;
        size_t src = (size_t)(b * LL + q0 + qq) * 576 + h * 32 + d0;
        *reinterpret_cast<uint4*>(&sQh[qq * QS + d0]) =
            *reinterpret_cast<const uint4*>(qh + src);
        *reinterpret_cast<uint4*>(&sQl[qq * QS + d0]) =
            *reinterpret_cast<const uint4*>(ql + src);
    }
    __syncthreads();

    uint32_t aQh[2], aQl[2];
#pragma unroll
    for (int mf = 0; mf < 2; mf++) {
        int r = mf * 16 + ((lane >> 3) & 1) * 8 + (lane & 7);
        int kc = (lane >> 4) * 8;
        aQh[mf] = smem_u32(&sQh[r * QS + kc]);
        aQl[mf] = smem_u32(&sQl[r * QS + kc]);
    }
    uint32_t aKh[2], aKl[2];
#pragma unroll
    for (int nf = 0; nf < 2; nf++) {
        int r = wid * 16 + nf * 8 + (lane & 7);
        int kc = ((lane >> 3) & 1) * 8;
        aKh[nf] = smem_u32(&sKh[r * KS + kc]);
        aKl[nf] = smem_u32(&sKl[r * KS + kc]);
    }

    const int g   = lane >> 2;
    const int tig = lane & 3;
    const int frow = tid >> 1;          // 0..127
    const int fh   = (tid & 1) * 16;

    // ---- QK^T chunks of 128 keys; bias fused into epilogue ----
    for (int kc0 = 0; kc0 < LL; kc0 += 128) {
        {   // K planes -> sKh/sKl (copies)
            size_t src = (size_t)(b * LL + kc0 + frow) * 576 + 192 + h * 32 + fh;
            *reinterpret_cast<uint4*>(&sKh[frow * KS + fh]) =
                *reinterpret_cast<const uint4*>(qh + src);
            *reinterpret_cast<uint4*>(&sKh[frow * KS + fh + 8]) =
                *reinterpret_cast<const uint4*>(qh + src + 8);
            *reinterpret_cast<uint4*>(&sKl[frow * KS + fh]) =
                *reinterpret_cast<const uint4*>(ql + src);
            *reinterpret_cast<uint4*>(&sKl[frow * KS + fh + 8]) =
                *reinterpret_cast<const uint4*>(ql + src + 8);
        }
        __syncthreads();

        float acc[2][2][4];
#pragma unroll
        for (int i = 0; i < 2; i++)
#pragma unroll
            for (int j = 0; j < 2; j++)
#pragma unroll
                for (int k = 0; k < 4; k++) acc[i][j][k] = 0.f;

#pragma unroll
        for (int ks = 0; ks < 2; ks++) {
            uint32_t ah[2][4], al[2][4], bh[2][2], bl[2][2];
            LDSM4(ah[0], aQh[0] + ks * 32);
            LDSM4(ah[1], aQh[1] + ks * 32);
            LDSM4(al[0], aQl[0] + ks * 32);
            LDSM4(al[1], aQl[1] + ks * 32);
            LDSM2(bh[0], aKh[0] + ks * 32);
            LDSM2(bh[1], aKh[1] + ks * 32);
            LDSM2(bl[0], aKl[0] + ks * 32);
            LDSM2(bl[1], aKl[1] + ks * 32);
#pragma unroll
            for (int mf = 0; mf < 2; mf++)
#pragma unroll
                for (int nf = 0; nf < 2; nf++) {
                    MMA16816(acc[mf][nf], ah[mf], bh[nf]);
                    MMA16816(acc[mf][nf], ah[mf], bl[nf]);
                    MMA16816(acc[mf][nf], al[mf], bh[nf]);
                }
        }

#pragma unroll
        for (int mf = 0; mf < 2; mf++)
#pragma unroll
            for (int nf = 0; nf < 2; nf++)
#pragma unroll
                for (int half = 0; half < 2; half++) {
                    int m = mf * 16 + g + half * 8;
                    int n = kc0 + wid * 16 + nf * 8 + 2 * tig;
                    int qg = q0 + m;
                    float2 bp = *reinterpret_cast<const float2*>(
                        &bppm[((size_t)(b * LL + qg)) * LL + n]);
                    float s0 = acc[mf][nf][half * 2 + 0] * scale + bp.x * pw
                             + srel[min(max(qg - n,     -32), 32) + 32] + cb;
                    float s1 = acc[mf][nf][half * 2 + 1] * scale + bp.y * pw
                             + srel[min(max(qg - n - 1, -32), 32) + 32] + cb;
                    *reinterpret_cast<float2*>(&sS[m * SP + n]) =
                        make_float2(s0, s1);
                }
        __syncthreads();
    }

    // ---- softmax (8 warps x 4 rows); emit P hi/lo IN-PLACE over sS ----
    for (int r = wid * 4; r < wid * 4 + 4; r++) {
        float* row = &sS[(size_t)r * SP];
        float vals[16];
        float mx = -1e30f;
#pragma unroll
        for (int j = 0; j < 16; j++) { vals[j] = row[lane + 32 * j]; mx = fmaxf(mx, vals[j]); }
#pragma unroll
        for (int of = 16; of; of >>= 1) mx = fmaxf(mx, __shfl_xor_sync(0xffffffffu, mx, of));
        float s = 0.f;
#pragma unroll
        for (int j = 0; j < 16; j++) { vals[j] = __expf(vals[j] - mx); s += vals[j]; }
#pragma unroll
        for (int of = 16; of; of >>= 1) s += __shfl_xor_sync(0xffffffffu, s, of);
        float inv = 1.0f / s;
        __syncwarp();
        uint8_t* rowb = uP + (size_t)r * SROWB;
#pragma unroll
        for (int j = 0; j < 16; j++) {
            float p = vals[j] * inv;
            __nv_bfloat16 hp = __float2bfloat16(p);
            float rem = p - __bfloat162float(hp);
            *(__nv_bfloat16*)(rowb + (lane + 32 * j) * 2) = hp;
            *(__nv_bfloat16*)(rowb + 1040 + (lane + 32 * j) * 2) = __float2bfloat16(rem);
        }
    }
    __syncthreads();

    // ---- PV: V planes fill sK region [k][d]; ldmatrix.trans as B operand ----
    const int mfw = wid >> 2;
    const int nfw = wid & 3;
    float c[4] = {0.f, 0.f, 0.f, 0.f};
    uint32_t aPh = smem_u32(uP +
        (size_t)(mfw * 16 + ((lane >> 3) & 1) * 8 + (lane & 7)) * SROWB
        + (lane >> 4) * 16);
    uint32_t aPl = aPh + 1040;
    uint32_t aVh = smem_u32(&sKh[(((lane >> 3) & 1) * 8 + (lane & 7)) * KS + nfw * 8]);
    uint32_t aVl = smem_u32(&sKl[(((lane >> 3) & 1) * 8 + (lane & 7)) * KS + nfw * 8]);

    for (int kc0 = 0; kc0 < LL; kc0 += 128) {
        {   // V planes -> sKh/sKl (copies, same layout as K)
            size_t src = (size_t)(b * LL + kc0 + frow) * 576 + 384 + h * 32 + fh;
            *reinterpret_cast<uint4*>(&sKh[frow * KS + fh]) =
                *reinterpret_cast<const uint4*>(qh + src);
            *reinterpret_cast<uint4*>(&sKh[frow * KS + fh + 8]) =
                *reinterpret_cast<const uint4*>(qh + src + 8);
            *reinterpret_cast<uint4*>(&sKl[frow * KS + fh]) =
                *reinterpret_cast<const uint4*>(ql + src);
            *reinterpret_cast<uint4*>(&sKl[frow * KS + fh + 8]) =
                *reinterpret_cast<const uint4*>(ql + src + 8);
        }
        __syncthreads();
#pragma unroll
        for (int ks = 0; ks < 8; ks++) {
            uint32_t ph[4], pl[4], vh[2], vl[2];
            uint32_t pofs = (uint32_t)(kc0 + ks * 16) * 2;
            LDSM4(ph, aPh + pofs);
            LDSM4(pl, aPl + pofs);
            LDSM2T(vh, aVh + ks * 16 * KS * 2);
            LDSM2T(vl, aVl + ks * 16 * KS * 2);
            MMA16816(c, ph, vh);
            MMA16816(c, ph, vl);
            MMA16816(c, pl, vh);
        }
        __syncthreads();
    }

    // ---- write O hi/lo planes ----
#pragma unroll
    for (int half = 0; half < 2; half++) {
        int m = mfw * 16 + g + half * 8;
        int n = nfw * 8 + 2 * tig;
        float rx = c[half * 2], ry = c[half * 2 + 1];
        __nv_bfloat162 hb = __floats2bfloat162_rn(rx, ry);
        float2 hf = __bfloat1622float2(hb);
        __nv_bfloat162 lb = __floats2bfloat162_rn(rx - hf.x, ry - hf.y);
        size_t dst = (size_t)(b * LL + q0 + m) * DDIM + h * 32 + n;
        *reinterpret_cast<uint32_t*>(oh + dst) = *(uint32_t*)&hb;
        *reinterpret_cast<uint32_t*>(ol + dst) = *(uint32_t*)&lb;
    }
}

// ---------------- final projection -------------------------------------------
__global__ __launch_bounds__(256) void proj_kernel(
    const float* __restrict__ x, const float* __restrict__ pw,
    const float* __restrict__ pb, float* __restrict__ out)
{
    int gtid = blockIdx.x * 256 + threadIdx.x;
    int row  = gtid >> 5;
    int lane = threadIdx.x & 31;
    const float* xr = x + (size_t)row * DDIM;
    float s0 = 0.f, s1 = 0.f;
#pragma unroll
    for (int j = 0; j < 6; j++) {
        int c = lane + 32 * j;
        float v = xr[c];
        s0 += v * pw[c];
        s1 += v * pw[DDIM + c];
    }
#pragma unroll
    for (int o = 16; o; o >>= 1) {
        s0 += __shfl_xor_sync(0xffffffffu, s0, o);
        s1 += __shfl_xor_sync(0xffffffffu, s1, o);
    }
    if (lane == 0) {
        out[(size_t)row * 2 + 0] = s0 + pb[0];
        out[(size_t)row * 2 + 1] = s1 + pb[1];
    }
}

// ---------------- launch ------------------------------------------------------
extern "C" void kernel_launch(void* const* d_in, const int* in_sizes, int n_in,
                              void* d_out, int out_size)
{
    (void)in_sizes; (void)n_in; (void)out_size;

    const int*   seq      = (const int*)  d_in[0];
    const float* bppm     = (const float*)d_in[2];
    const float* emb      = (const float*)d_in[3];
    const float* pair_w   = (const float*)d_in[4];
    const float* pair_b   = (const float*)d_in[5];
    const float* relpos_w = (const float*)d_in[6];
    const float* relpos_b = (const float*)d_in[7];
    const float* ln1_s    = (const float*)d_in[8];
    const float* ln1_b    = (const float*)d_in[9];
    const float* qkv_w    = (const float*)d_in[10];
    const float* qkv_b    = (const float*)d_in[11];
    const float* out_w    = (const float*)d_in[12];
    const float* out_b    = (const float*)d_in[13];
    const float* ln2_s    = (const float*)d_in[14];
    const float* ln2_b    = (const float*)d_in[15];
    const float* ff1_w    = (const float*)d_in[16];
    const float* ff1_b    = (const float*)d_in[17];
    const float* ff2_w    = (const float*)d_in[18];
    const float* ff2_b    = (const float*)d_in[19];
    const float* proj_w   = (const float*)d_in[20];
    const float* proj_b   = (const float*)d_in[21];
    float*       out      = (float*)d_out;

    void* p;
    cudaGetSymbolAddress(&p, g_x);   float* px = (float*)p;
    cudaGetSymbolAddress(&p, g_hh);  __nv_bfloat16* phh = (__nv_bfloat16*)p;
    cudaGetSymbolAddress(&p, g_hl);  __nv_bfloat16* phl = (__nv_bfloat16*)p;
    cudaGetSymbolAddress(&p, g_qh);  __nv_bfloat16* pqh = (__nv_bfloat16*)p;
    cudaGetSymbolAddress(&p, g_ql);  __nv_bfloat16* pql = (__nv_bfloat16*)p;
    cudaGetSymbolAddress(&p, g_oh);  __nv_bfloat16* poh = (__nv_bfloat16*)p;
    cudaGetSymbolAddress(&p, g_ol);  __nv_bfloat16* pol = (__nv_bfloat16*)p;
    cudaGetSymbolAddress(&p, g_fh);  __nv_bfloat16* pfh = (__nv_bfloat16*)p;
    cudaGetSymbolAddress(&p, g_fl);  __nv_bfloat16* pfl = (__nv_bfloat16*)p;
    cudaGetSymbolAddress(&p, g_wqh); __nv_bfloat16* wqh = (__nv_bfloat16*)p;
    cudaGetSymbolAddress(&p, g_wql); __nv_bfloat16* wql = (__nv_bfloat16*)p;
    cudaGetSymbolAddress(&p, g_woh); __nv_bfloat16* woh = (__nv_bfloat16*)p;
    cudaGetSymbolAddress(&p, g_wol); __nv_bfloat16* wol = (__nv_bfloat16*)p;
    cudaGetSymbolAddress(&p, g_w1h); __nv_bfloat16* w1h = (__nv_bfloat16*)p;
    cudaGetSymbolAddress(&p, g_w1l); __nv_bfloat16* w1l = (__nv_bfloat16*)p;
    cudaGetSymbolAddress(&p, g_w2h); __nv_bfloat16* w2h = (__nv_bfloat16*)p;
    cudaGetSymbolAddress(&p, g_w2l); __nv_bfloat16* w2l = (__nv_bfloat16*)p;

    cudaFuncSetAttribute(attn_kernel,
        cudaFuncAttributeMaxDynamicSharedMemorySize, ATTN_SMEM_BYTES);

    // weight plane conversion (layer-constant; cheap)
    {
        int n8q = NDEPTH * 576 * 192 / 8;
        int n8o = NDEPTH * 192 * 192 / 8;
        int n8f = NDEPTH * 768 * 192 / 8;
        convw_kernel<<<(n8q + 255) / 256, 256>>>(qkv_w, wqh, wql, n8q);
        convw_kernel<<<(n8o + 255) / 256, 256>>>(out_w, woh, wol, n8o);
        convw_kernel<<<(n8f + 255) / 256, 256>>>(ff1_w, w1h, w1l, n8f);
        convw_kernel<<<(n8f + 255) / 256, 256>>>(ff2_w, w2h, w2l, n8f);
    }

    embed_kernel<<<(NROWS * DDIM) / 256, 256>>>(seq, emb, px);

    for (int i = 0; i < NDEPTH; i++) {
        ln_kernel<<<2048, 256>>>(px, ln1_s + i * DDIM, ln1_b + i * DDIM, phh, phl);

        gemm_mma<3><<<dim3(9, 128), 256>>>(
            phh, phl, wqh + (size_t)i * 576 * 192, wql + (size_t)i * 576 * 192,
            qkv_b + (size_t)i * 576, nullptr, nullptr, pqh, pql, 576, 192);

        attn_kernel<<<dim3(16, 6, 32), 256, ATTN_SMEM_BYTES>>>(
            pqh, pql, bppm, pair_w, pair_b, relpos_w, relpos_b, poh, pol);

        gemm_mma<2><<<dim3(3, 128), 256>>>(
            poh, pol, woh + (size_t)i * 192 * 192, wol + (size_t)i * 192 * 192,
            out_b + (size_t)i * DDIM, px, px, nullptr, nullptr, 192, 192);

        ln_kernel<<<2048, 256>>>(px, ln2_s + i * DDIM, ln2_b + i * DDIM, phh, phl);

        gemm_mma<1><<<dim3(12, 128), 256>>>(
            phh, phl, w1h + (size_t)i * 768 * 192, w1l + (size_t)i * 768 * 192,
            ff1_b + (size_t)i * 768, nullptr, nullptr, pfh, pfl, 768, 192);

        gemm_mma<2><<<dim3(3, 128), 256>>>(
            pfh, pfl, w2h + (size_t)i * 192 * 768, w2l + (size_t)i * 192 * 768,
            ff2_b + (size_t)i * DDIM, px, px, nullptr, nullptr, 192, 768);
    }

    proj_kernel<<<2048, 256>>>(px, proj_w, proj_b, out);
}

// round 15
// speedup vs baseline: 1.3631x; 1.3631x over previous
#include <cuda_runtime.h>
#include <cuda_bf16.h>
#include <math.h>
#include <stdint.h>

#define BB     32
#define LL     512
#define DDIM   192
#define HH     6
#define NDEPTH 12
#define NROWS  (BB * LL)          // 16384

// ---------------- scratch (device globals) ----------------------------------
__device__ __align__(16) float g_x  [NROWS * DDIM];
__device__ __align__(16) float g_h  [NROWS * DDIM];
__device__ __align__(16) float g_qkv[NROWS * 3 * DDIM];
__device__ __align__(16) float g_o  [NROWS * DDIM];
__device__ __align__(16) float g_ff [NROWS * 4 * DDIM];

// ---------------- helpers ----------------------------------------------------
__device__ __forceinline__ uint32_t smem_u32(const void* p) {
    uint32_t a;
    asm("{ .reg .u64 t; cvta.to.shared.u64 t, %1; cvt.u32.u64 %0, t; }"
        : "=r"(a) : "l"(p));
    return a;
}

// fp32x8 -> bf16 hi plane + lo plane (16B each)
__device__ __forceinline__ void cvt8(__nv_bfloat16* ph, __nv_bfloat16* pl,
                                     float4 a, float4 b) {
    __nv_bfloat162 h0 = __floats2bfloat162_rn(a.x, a.y);
    __nv_bfloat162 h1 = __floats2bfloat162_rn(a.z, a.w);
    __nv_bfloat162 h2 = __floats2bfloat162_rn(b.x, b.y);
    __nv_bfloat162 h3 = __floats2bfloat162_rn(b.z, b.w);
    float2 f0 = __bfloat1622float2(h0), f1 = __bfloat1622float2(h1);
    float2 f2 = __bfloat1622float2(h2), f3 = __bfloat1622float2(h3);
    __nv_bfloat162 l0 = __floats2bfloat162_rn(a.x - f0.x, a.y - f0.y);
    __nv_bfloat162 l1 = __floats2bfloat162_rn(a.z - f1.x, a.w - f1.y);
    __nv_bfloat162 l2 = __floats2bfloat162_rn(b.x - f2.x, b.y - f2.y);
    __nv_bfloat162 l3 = __floats2bfloat162_rn(b.z - f3.x, b.w - f3.y);
    uint4 hv, lv;
    hv.x = *(uint32_t*)&h0; hv.y = *(uint32_t*)&h1;
    hv.z = *(uint32_t*)&h2; hv.w = *(uint32_t*)&h3;
    lv.x = *(uint32_t*)&l0; lv.y = *(uint32_t*)&l1;
    lv.z = *(uint32_t*)&l2; lv.w = *(uint32_t*)&l3;
    *reinterpret_cast<uint4*>(ph) = hv;
    *reinterpret_cast<uint4*>(pl) = lv;
}

// fp32 pair -> packed bf16 hi + lo words
__device__ __forceinline__ void split2(float x, float y,
                                       uint32_t& hi, uint32_t& lo) {
    __nv_bfloat162 hb = __floats2bfloat162_rn(x, y);
    float2 hf = __bfloat1622float2(hb);
    __nv_bfloat162 lb = __floats2bfloat162_rn(x - hf.x, y - hf.y);
    hi = *(uint32_t*)&hb;
    lo = *(uint32_t*)&lb;
}

#define LDSM4(r, addr) \
    asm volatile("ldmatrix.sync.aligned.m8n8.x4.shared.b16 {%0,%1,%2,%3}, [%4];" \
        : "=r"((r)[0]), "=r"((r)[1]), "=r"((r)[2]), "=r"((r)[3]) : "r"(addr))
#define LDSM2(r, addr) \
    asm volatile("ldmatrix.sync.aligned.m8n8.x2.shared.b16 {%0,%1}, [%2];" \
        : "=r"((r)[0]), "=r"((r)[1]) : "r"(addr))
#define LDSM2T(r, addr) \
    asm volatile("ldmatrix.sync.aligned.m8n8.x2.trans.shared.b16 {%0,%1}, [%2];" \
        : "=r"((r)[0]), "=r"((r)[1]) : "r"(addr))
#define MMA16816(c, a, b) \
    asm volatile("mma.sync.aligned.m16n8k16.row.col.f32.bf16.bf16.f32 " \
        "{%0,%1,%2,%3}, {%4,%5,%6,%7}, {%8,%9}, {%0,%1,%2,%3};" \
        : "+f"((c)[0]), "+f"((c)[1]), "+f"((c)[2]), "+f"((c)[3]) \
        : "r"((a)[0]), "r"((a)[1]), "r"((a)[2]), "r"((a)[3]), \
          "r"((b)[0]), "r"((b)[1]))

// ---------------- embedding --------------------------------------------------
__global__ __launch_bounds__(256) void embed_kernel(
    const int* __restrict__ seq, const float* __restrict__ emb,
    float* __restrict__ x)
{
    int idx = blockIdx.x * 256 + threadIdx.x;
    int r = idx / DDIM;
    int c = idx - r * DDIM;
    x[idx] = emb[seq[r] * DDIM + c];
}

// ---------------- layernorm --------------------------------------------------
__global__ __launch_bounds__(256) void ln_kernel(
    const float* __restrict__ x, const float* __restrict__ gam,
    const float* __restrict__ bet, float* __restrict__ out)
{
    int gtid = blockIdx.x * 256 + threadIdx.x;
    int row  = gtid >> 5;
    int lane = threadIdx.x & 31;
    const float* xr = x + (size_t)row * DDIM;
    float v[6];
    float s = 0.f;
#pragma unroll
    for (int j = 0; j < 6; j++) { v[j] = xr[lane + 32 * j]; s += v[j]; }
#pragma unroll
    for (int o = 16; o; o >>= 1) s += __shfl_xor_sync(0xffffffffu, s, o);
    float mu = s * (1.0f / DDIM);
    float sq = 0.f;
#pragma unroll
    for (int j = 0; j < 6; j++) { float d = v[j] - mu; sq += d * d; }
#pragma unroll
    for (int o = 16; o; o >>= 1) sq += __shfl_xor_sync(0xffffffffu, sq, o);
    float rstd = rsqrtf(sq * (1.0f / DDIM) + 1e-5f);
    float* orow = out + (size_t)row * DDIM;
#pragma unroll
    for (int j = 0; j < 6; j++) {
        int c = lane + 32 * j;
        orow[c] = (v[j] - mu) * rstd * gam[c] + bet[c];
    }
}

// ---------------- mma.sync bf16-split GEMM: C = A @ W^T + bias ---------------
#define GMS 40

template<int EPI>
__global__ __launch_bounds__(256, 2) void gemm_mma(
    const float* __restrict__ A, const float* __restrict__ W,
    const float* __restrict__ bias, const float* __restrict__ resid,
    float* __restrict__ C, int N, int K)
{
    __shared__ __nv_bfloat16 sAh[128 * GMS];
    __shared__ __nv_bfloat16 sAl[128 * GMS];
    __shared__ __nv_bfloat16 sWh[64 * GMS];
    __shared__ __nv_bfloat16 sWl[64 * GMS];

    const int tid  = threadIdx.x;
    const int wid  = tid >> 5;
    const int lane = tid & 31;
    const int m0 = blockIdx.y * 128;
    const int n0 = blockIdx.x * 64;
    const int wm = wid & 3;
    const int wn = wid >> 2;

    float acc[2][4][4];
#pragma unroll
    for (int i = 0; i < 2; i++)
#pragma unroll
        for (int j = 0; j < 4; j++)
#pragma unroll
            for (int k = 0; k < 4; k++) acc[i][j][k] = 0.f;

    uint32_t adrA[2], adrAl[2];
#pragma unroll
    for (int mf = 0; mf < 2; mf++) {
        int r  = wm * 32 + mf * 16 + ((lane >> 3) & 1) * 8 + (lane & 7);
        int kc = (lane >> 4) * 8;
        adrA[mf]  = smem_u32(&sAh[r * GMS + kc]);
        adrAl[mf] = smem_u32(&sAl[r * GMS + kc]);
    }
    uint32_t adrB[4], adrBl[4];
#pragma unroll
    for (int nf = 0; nf < 4; nf++) {
        int r  = wn * 32 + nf * 8 + (lane & 7);
        int kc = ((lane >> 3) & 1) * 8;
        adrB[nf]  = smem_u32(&sWh[r * GMS + kc]);
        adrBl[nf] = smem_u32(&sWl[r * GMS + kc]);
    }

    const int lrow = tid >> 2;
    const int lsec = tid & 3;

    for (int k0 = 0; k0 < K; k0 += 32) {
        {
            const float* ap = A + (size_t)(m0 + lrow) * K + k0 + lsec * 8;
            cvt8(&sAh[lrow * GMS + lsec * 8], &sAl[lrow * GMS + lsec * 8],
                 *reinterpret_cast<const float4*>(ap),
                 *reinterpret_cast<const float4*>(ap + 4));
            const float* ap2 = A + (size_t)(m0 + 64 + lrow) * K + k0 + lsec * 8;
            cvt8(&sAh[(64 + lrow) * GMS + lsec * 8], &sAl[(64 + lrow) * GMS + lsec * 8],
                 *reinterpret_cast<const float4*>(ap2),
                 *reinterpret_cast<const float4*>(ap2 + 4));
            const float* wp = W + (size_t)(n0 + lrow) * K + k0 + lsec * 8;
            cvt8(&sWh[lrow * GMS + lsec * 8], &sWl[lrow * GMS + lsec * 8],
                 *reinterpret_cast<const float4*>(wp),
                 *reinterpret_cast<const float4*>(wp + 4));
        }
        __syncthreads();

#pragma unroll
        for (int kk = 0; kk < 2; kk++) {
            uint32_t ah[2][4], al[2][4], bh[4][2], bl[4][2];
            const uint32_t ko = kk * 32;
#pragma unroll
            for (int mf = 0; mf < 2; mf++) {
                LDSM4(ah[mf], adrA[mf] + ko);
                LDSM4(al[mf], adrAl[mf] + ko);
            }
#pragma unroll
            for (int nf = 0; nf < 4; nf++) {
                LDSM2(bh[nf], adrB[nf] + ko);
                LDSM2(bl[nf], adrBl[nf] + ko);
            }
#pragma unroll
            for (int mf = 0; mf < 2; mf++)
#pragma unroll
                for (int nf = 0; nf < 4; nf++) {
                    MMA16816(acc[mf][nf], ah[mf], bh[nf]);
                    MMA16816(acc[mf][nf], ah[mf], bl[nf]);
                    MMA16816(acc[mf][nf], al[mf], bh[nf]);
                }
        }
        __syncthreads();
    }

    const int g   = lane >> 2;
    const int tig = lane & 3;
#pragma unroll
    for (int mf = 0; mf < 2; mf++) {
#pragma unroll
        for (int nf = 0; nf < 4; nf++) {
            int m = m0 + wm * 32 + mf * 16 + g;
            int n = n0 + wn * 32 + nf * 8 + 2 * tig;
            float b0 = bias[n], b1 = bias[n + 1];
#pragma unroll
            for (int half = 0; half < 2; half++) {
                int mm = m + half * 8;
                float2 r;
                r.x = acc[mf][nf][half * 2 + 0] + b0;
                r.y = acc[mf][nf][half * 2 + 1] + b1;
                if (EPI == 1) {
                    r.x = 0.5f * r.x * (1.0f + erff(r.x * 0.70710678118654752f));
                    r.y = 0.5f * r.y * (1.0f + erff(r.y * 0.70710678118654752f));
                }
                if (EPI == 2) {
                    float2 rv = *reinterpret_cast<const float2*>(
                        &resid[(size_t)mm * N + n]);
                    r.x += rv.x; r.y += rv.y;
                }
                *reinterpret_cast<float2*>(&C[(size_t)mm * N + n]) = r;
            }
        }
    }
}

// ---------------- flash attention (register-resident, hi/lo split) -----------
// Block = (128-q tile, head, batch), 8 warps; warp w owns q rows w*16..w*16+15
// x all 32 d. Online softmax over K chunks of 64; QK C-fragments repacked
// directly into PV A-fragments (P never touches SMEM). All operands hi/lo
// split with 3-term MMA (matches R11 numerics).
#define AS 40   // smem row stride (bf16 units)

__global__ __launch_bounds__(256) void attn_kernel(
    const float* __restrict__ qkv, const float* __restrict__ bppm,
    const float* __restrict__ pair_w, const float* __restrict__ pair_b,
    const float* __restrict__ relpos_w, const float* __restrict__ relpos_b,
    float* __restrict__ o)
{
    __shared__ __nv_bfloat16 sQh[128 * AS], sQl[128 * AS];
    __shared__ __nv_bfloat16 sKh[64 * AS],  sKl[64 * AS];
    __shared__ __nv_bfloat16 sVh[64 * AS],  sVl[64 * AS];
    __shared__ float srel[68];

    const int tid  = threadIdx.x;
    const int wid  = tid >> 5;
    const int lane = tid & 31;
    const int q0 = blockIdx.x * 128;
    const int h  = blockIdx.y;
    const int b  = blockIdx.z;

    if (tid < 65) srel[tid] = relpos_w[h * 65 + tid];
    const float pw = pair_w[h];
    const float cb = pair_b[h] + relpos_b[h];
    const float scale = 0.17677669529663687f;   // 1/sqrt(32)

    // ---- Q fill (fp32 -> hi/lo planes) ----
    {
        int qq = tid >> 1, sec = (tid & 1) * 16;
        const float* qb = qkv + (size_t)(b * LL + q0 + qq) * 576 + h * 32 + sec;
        cvt8(&sQh[qq * AS + sec], &sQl[qq * AS + sec],
             *reinterpret_cast<const float4*>(qb),
             *reinterpret_cast<const float4*>(qb + 4));
        cvt8(&sQh[qq * AS + sec + 8], &sQl[qq * AS + sec + 8],
             *reinterpret_cast<const float4*>(qb + 8),
             *reinterpret_cast<const float4*>(qb + 12));
    }
    __syncthreads();

    // ---- Q fragments (chunk-invariant, kept in registers) ----
    uint32_t qfh[2][4], qfl[2][4];
    {
        int r  = wid * 16 + ((lane >> 3) & 1) * 8 + (lane & 7);
        int kc = (lane >> 4) * 8;
        uint32_t a = smem_u32(&sQh[r * AS + kc]);
        LDSM4(qfh[0], a); LDSM4(qfh[1], a + 32);
        a = smem_u32(&sQl[r * AS + kc]);
        LDSM4(qfl[0], a); LDSM4(qfl[1], a + 32);
    }

    const int g   = lane >> 2;
    const int tig = lane & 3;
    const int qgA = q0 + wid * 16 + g;        // row of c0,c1 (c2,c3: +8)
    const int rB  = lane & 7;                 // K B-frag row within 8-block
    const int kcB = ((lane >> 3) & 1) * 8;    // K B-frag d-half
    const int rV  = ((lane >> 3) & 1) * 8 + (lane & 7);   // V trans rows

    float m0v = -1e30f, m1v = -1e30f, l0v = 0.f, l1v = 0.f;
    float O[4][4];
#pragma unroll
    for (int i = 0; i < 4; i++)
#pragma unroll
        for (int j = 0; j < 4; j++) O[i][j] = 0.f;

    const int frow = tid >> 2;          // 0..63  (K/V fill)
    const int fsec = (tid & 3) * 8;

    for (int kc0 = 0; kc0 < LL; kc0 += 64) {
        // ---- K/V chunk fill ----
        {
            const float* kb = qkv + (size_t)(b * LL + kc0 + frow) * 576
                              + 192 + h * 32 + fsec;
            cvt8(&sKh[frow * AS + fsec], &sKl[frow * AS + fsec],
                 *reinterpret_cast<const float4*>(kb),
                 *reinterpret_cast<const float4*>(kb + 4));
            const float* vb = kb + 192;
            cvt8(&sVh[frow * AS + fsec], &sVl[frow * AS + fsec],
                 *reinterpret_cast<const float4*>(vb),
                 *reinterpret_cast<const float4*>(vb + 4));
        }
        __syncthreads();

        // ---- QK^T: 8 n-fragments in registers ----
        float S[8][4];
#pragma unroll
        for (int nf = 0; nf < 8; nf++)
#pragma unroll
            for (int j = 0; j < 4; j++) S[nf][j] = 0.f;
#pragma unroll
        for (int ks = 0; ks < 2; ks++)
#pragma unroll
            for (int nf = 0; nf < 8; nf++) {
                uint32_t bh[2], bl[2];
                LDSM2(bh, smem_u32(&sKh[(nf * 8 + rB) * AS + kcB]) + ks * 32);
                LDSM2(bl, smem_u32(&sKl[(nf * 8 + rB) * AS + kcB]) + ks * 32);
                MMA16816(S[nf], qfh[ks], bh);
                MMA16816(S[nf], qfh[ks], bl);
                MMA16816(S[nf], qfl[ks], bh);
            }

        // ---- bias + scale ----
#pragma unroll
        for (int nf = 0; nf < 8; nf++) {
            int n = kc0 + nf * 8 + 2 * tig;
            float2 bp0 = *reinterpret_cast<const float2*>(
                &bppm[(size_t)(b * LL + qgA) * LL + n]);
            float2 bp1 = *reinterpret_cast<const float2*>(
                &bppm[(size_t)(b * LL + qgA + 8) * LL + n]);
            S[nf][0] = S[nf][0] * scale + bp0.x * pw
                     + srel[min(max(qgA - n,         -32), 32) + 32] + cb;
            S[nf][1] = S[nf][1] * scale + bp0.y * pw
                     + srel[min(max(qgA - n - 1,     -32), 32) + 32] + cb;
            S[nf][2] = S[nf][2] * scale + bp1.x * pw
                     + srel[min(max(qgA + 8 - n,     -32), 32) + 32] + cb;
            S[nf][3] = S[nf][3] * scale + bp1.y * pw
                     + srel[min(max(qgA + 8 - n - 1, -32), 32) + 32] + cb;
        }

        // ---- online softmax update (rows g and g+8) ----
        float cm0 = -1e30f, cm1 = -1e30f;
#pragma unroll
        for (int nf = 0; nf < 8; nf++) {
            cm0 = fmaxf(cm0, fmaxf(S[nf][0], S[nf][1]));
            cm1 = fmaxf(cm1, fmaxf(S[nf][2], S[nf][3]));
        }
        cm0 = fmaxf(cm0, __shfl_xor_sync(0xffffffffu, cm0, 1));
        cm0 = fmaxf(cm0, __shfl_xor_sync(0xffffffffu, cm0, 2));
        cm1 = fmaxf(cm1, __shfl_xor_sync(0xffffffffu, cm1, 1));
        cm1 = fmaxf(cm1, __shfl_xor_sync(0xffffffffu, cm1, 2));
        float nm0 = fmaxf(m0v, cm0), nm1 = fmaxf(m1v, cm1);
        float a0 = __expf(m0v - nm0), a1 = __expf(m1v - nm1);
        m0v = nm0; m1v = nm1;
        float cs0 = 0.f, cs1 = 0.f;
#pragma unroll
        for (int nf = 0; nf < 8; nf++) {
            S[nf][0] = __expf(S[nf][0] - nm0);
            S[nf][1] = __expf(S[nf][1] - nm0);
            S[nf][2] = __expf(S[nf][2] - nm1);
            S[nf][3] = __expf(S[nf][3] - nm1);
            cs0 += S[nf][0] + S[nf][1];
            cs1 += S[nf][2] + S[nf][3];
        }
        cs0 += __shfl_xor_sync(0xffffffffu, cs0, 1);
        cs0 += __shfl_xor_sync(0xffffffffu, cs0, 2);
        cs1 += __shfl_xor_sync(0xffffffffu, cs1, 1);
        cs1 += __shfl_xor_sync(0xffffffffu, cs1, 2);
        l0v = l0v * a0 + cs0;
        l1v = l1v * a1 + cs1;
#pragma unroll
        for (int nf = 0; nf < 4; nf++) {
            O[nf][0] *= a0; O[nf][1] *= a0;
            O[nf][2] *= a1; O[nf][3] *= a1;
        }

        // ---- P·V: repack S fragments as A operands; V via ldmatrix.trans ----
#pragma unroll
        for (int s = 0; s < 4; s++) {
            uint32_t ph[4], pl[4];
            split2(S[2 * s][0],     S[2 * s][1],     ph[0], pl[0]);
            split2(S[2 * s][2],     S[2 * s][3],     ph[1], pl[1]);
            split2(S[2 * s + 1][0], S[2 * s + 1][1], ph[2], pl[2]);
            split2(S[2 * s + 1][2], S[2 * s + 1][3], ph[3], pl[3]);
#pragma unroll
            for (int nf = 0; nf < 4; nf++) {
                uint32_t vh[2], vl[2];
                LDSM2T(vh, smem_u32(&sVh[(s * 16 + rV) * AS + nf * 8]));
                LDSM2T(vl, smem_u32(&sVl[(s * 16 + rV) * AS + nf * 8]));
                MMA16816(O[nf], ph, vh);
                MMA16816(O[nf], ph, vl);
                MMA16816(O[nf], pl, vh);
            }
        }
        __syncthreads();
    }

    // ---- normalize + write ----
    float inv0 = 1.0f / l0v, inv1 = 1.0f / l1v;
#pragma unroll
    for (int nf = 0; nf < 4; nf++) {
        int n = nf * 8 + 2 * tig;
        *reinterpret_cast<float2*>(
            &o[(size_t)(b * LL + qgA) * DDIM + h * 32 + n]) =
            make_float2(O[nf][0] * inv0, O[nf][1] * inv0);
        *reinterpret_cast<float2*>(
            &o[(size_t)(b * LL + qgA + 8) * DDIM + h * 32 + n]) =
            make_float2(O[nf][2] * inv1, O[nf][3] * inv1);
    }
}

// ---------------- final projection -------------------------------------------
__global__ __launch_bounds__(256) void proj_kernel(
    const float* __restrict__ x, const float* __restrict__ pw,
    const float* __restrict__ pb, float* __restrict__ out)
{
    int gtid = blockIdx.x * 256 + threadIdx.x;
    int row  = gtid >> 5;
    int lane = threadIdx.x & 31;
    const float* xr = x + (size_t)row * DDIM;
    float s0 = 0.f, s1 = 0.f;
#pragma unroll
    for (int j = 0; j < 6; j++) {
        int c = lane + 32 * j;
        float v = xr[c];
        s0 += v * pw[c];
        s1 += v * pw[DDIM + c];
    }
#pragma unroll
    for (int o = 16; o; o >>= 1) {
        s0 += __shfl_xor_sync(0xffffffffu, s0, o);
        s1 += __shfl_xor_sync(0xffffffffu, s1, o);
    }
    if (lane == 0) {
        out[(size_t)row * 2 + 0] = s0 + pb[0];
        out[(size_t)row * 2 + 1] = s1 + pb[1];
    }
}

// ---------------- launch ------------------------------------------------------
extern "C" void kernel_launch(void* const* d_in, const int* in_sizes, int n_in,
                              void* d_out, int out_size)
{
    (void)in_sizes; (void)n_in; (void)out_size;

    const int*   seq      = (const int*)  d_in[0];
    const float* bppm     = (const float*)d_in[2];
    const float* emb      = (const float*)d_in[3];
    const float* pair_w   = (const float*)d_in[4];
    const float* pair_b   = (const float*)d_in[5];
    const float* relpos_w = (const float*)d_in[6];
    const float* relpos_b = (const float*)d_in[7];
    const float* ln1_s    = (const float*)d_in[8];
    const float* ln1_b    = (const float*)d_in[9];
    const float* qkv_w    = (const float*)d_in[10];
    const float* qkv_b    = (const float*)d_in[11];
    const float* out_w    = (const float*)d_in[12];
    const float* out_b    = (const float*)d_in[13];
    const float* ln2_s    = (const float*)d_in[14];
    const float* ln2_b    = (const float*)d_in[15];
    const float* ff1_w    = (const float*)d_in[16];
    const float* ff1_b    = (const float*)d_in[17];
    const float* ff2_w    = (const float*)d_in[18];
    const float* ff2_b    = (const float*)d_in[19];
    const float* proj_w   = (const float*)d_in[20];
    const float* proj_b   = (const float*)d_in[21];
    float*       out      = (float*)d_out;

    void* p;
    cudaGetSymbolAddress(&p, g_x);   float* px   = (float*)p;
    cudaGetSymbolAddress(&p, g_h);   float* ph   = (float*)p;
    cudaGetSymbolAddress(&p, g_qkv); float* pqkv = (float*)p;
    cudaGetSymbolAddress(&p, g_o);   float* po   = (float*)p;
    cudaGetSymbolAddress(&p, g_ff);  float* pff  = (float*)p;

    embed_kernel<<<(NROWS * DDIM) / 256, 256>>>(seq, emb, px);

    for (int i = 0; i < NDEPTH; i++) {
        ln_kernel<<<2048, 256>>>(px, ln1_s + i * DDIM, ln1_b + i * DDIM, ph);

        gemm_mma<0><<<dim3(9, 128), 256>>>(
            ph, qkv_w + (size_t)i * 576 * DDIM, qkv_b + (size_t)i * 576,
            nullptr, pqkv, 576, 192);

        attn_kernel<<<dim3(4, 6, 32), 256>>>(
            pqkv, bppm, pair_w, pair_b, relpos_w, relpos_b, po);

        gemm_mma<2><<<dim3(3, 128), 256>>>(
            po, out_w + (size_t)i * DDIM * DDIM, out_b + (size_t)i * DDIM,
            px, px, 192, 192);

        ln_kernel<<<2048, 256>>>(px, ln2_s + i * DDIM, ln2_b + i * DDIM, ph);

        gemm_mma<1><<<dim3(12, 128), 256>>>(
            ph, ff1_w + (size_t)i * 768 * DDIM, ff1_b + (size_t)i * 768,
            nullptr, pff, 768, 192);

        gemm_mma<2><<<dim3(3, 128), 256>>>(
            pff, ff2_w + (size_t)i * DDIM * 768, ff2_b + (size_t)i * DDIM,
            px, px, 192, 768);
    }

    proj_kernel<<<2048, 256>>>(px, proj_w, proj_b, out);
}